// round 13
// baseline (speedup 1.0000x reference)
#include <cuda_runtime.h>
#include <cuda_fp16.h>
#include <math.h>
#include <stdint.h>

#define N_PIX (512 * 512)
#define NTHR  256
#define MTHR  512

// ---------------------------------------------------------------------------
// Device scratch (no allocations allowed)
// ---------------------------------------------------------------------------
__device__ float    g_b1eff[512];        // b1f + phi_t @ W1f[40:,:]
__device__ float    g_Ax[512 * 512];     // posenc_x(c) @ W1f[0:20,:]
__device__ float    g_Ay[512 * 512];     // posenc_y(c) @ W1f[20:40,:]
__device__ uint32_t g_W2H[512 * 256];    // W2 fp16, uint4-fragment-major

// m16n8k16 fp16 mma, fp32 acc
#define MMA_F16(d, a, b0, b1)                                                  \
    asm volatile("mma.sync.aligned.m16n8k16.row.col.f32.f16.f16.f32 "          \
                 "{%0,%1,%2,%3},{%4,%5,%6,%7},{%8,%9},{%0,%1,%2,%3};"          \
                 : "+f"((d)[0]), "+f"((d)[1]), "+f"((d)[2]), "+f"((d)[3])      \
                 : "r"((a).x), "r"((a).y), "r"((a).z), "r"((a).w),             \
                   "r"(b0), "r"(b1))

__device__ __forceinline__ uint32_t h2u(float a, float b) {
    __half2 h = __floats2half2_rn(a, b);
    return *(uint32_t*)&h;
}
__device__ __forceinline__ float relu_f(float x) { return fmaxf(x, 0.0f); }

// ---------------------------------------------------------------------------
// Accurate sin/cos (flag-independent): Cody-Waite in double + Cephes fp32
// ---------------------------------------------------------------------------
__device__ __forceinline__ float trig_eval(float x, int cos_flag) {
    double d  = (double)x * 0.63661977236758134308;
    int    ki = __double2int_rn(d);
    float  rf = (float)((double)x - (double)ki * 1.57079632679489661923);
    int    q  = (ki + cos_flag) & 3;
    float  z  = rf * rf;
    float s = ((-1.9515295891e-4f * z + 8.3321608736e-3f) * z - 1.6666654611e-1f)
                  * z * rf + rf;
    float c = ((2.443315711809948e-5f * z - 1.388731625493765e-3f) * z
                  + 4.166664568298827e-2f) * z * z - 0.5f * z + 1.0f;
    float res = (q & 1) ? c : s;
    return (q & 2) ? -res : res;
}

// ---------------------------------------------------------------------------
// Prep (single launch, 1537 blocks): tables, W2H packing, time branch.
// W2H packing for element (n, k), value W2f[k*512+n]:
//   k16=k>>4, lane=(n&7)*4+((k&7)>>1), reg=(k>>3)&1, np=(n>>4), o=(n>>3)&1
//   uint4 index = (k16*32 + np)*32 + lane,  component = o*2 + reg
// ---------------------------------------------------------------------------
__global__ void nivr_prep_kernel(const float* __restrict__ W1p,
                                 const float* __restrict__ b1p,
                                 const float* __restrict__ W2p,
                                 const float* __restrict__ b2p,
                                 const float* __restrict__ W1f,
                                 const float* __restrict__ b1f,
                                 const float* __restrict__ W2f,
                                 const int*   __restrict__ idx_p) {
    const int b = blockIdx.x, tid = threadIdx.x;
    if (b < 1024) {
        const int axis = b >> 9;
        const int c    = b & 511;
        __shared__ float pe[20];
        if (tid < 20) {
            int l = tid % 10;
            float ang = (((float)c * (1.0f / 512.0f)) * (float)(1 << l))
                            * 3.14159265358979323846f;
            pe[tid] = trig_eval(ang, tid >= 10);
        }
        __syncthreads();
        const float* Wr  = W1f + axis * 20 * 512;
        float*       dst = (axis ? g_Ay : g_Ax) + c * 512;
        for (int j = tid; j < 512; j += NTHR) {
            float acc = 0.0f;
            #pragma unroll
            for (int f = 0; f < 20; f++)
                acc = fmaf(pe[f], Wr[f * 512 + j], acc);
            dst[j] = acc;
        }
    } else if (b < 1536) {
        const int n  = b - 1024;
        const int k  = tid * 2;             // even k; pack (k, k+1)
        float lo = W2f[(size_t)k * 512 + n];
        float hi = W2f[(size_t)(k + 1) * 512 + n];
        int k16  = k >> 4;
        int lane = (n & 7) * 4 + ((k & 7) >> 1);
        int reg  = (k >> 3) & 1;
        int idx4 = (k16 * 32 + (n >> 4)) * 32 + lane;
        int comp = ((n >> 3) & 1) * 2 + reg;
        g_W2H[idx4 * 4 + comp] = h2u(lo, hi);
    } else {
        __shared__ float sr[32];
        __shared__ float sh[256];
        __shared__ float sphi[128];
        float t = (float)(*idx_p) / 300.0f;
        if (tid < 32) {
            int l = tid & 15;
            float ang = (t * (float)(1 << l)) * 3.14159265358979323846f;
            sr[tid] = trig_eval(ang, tid >= 16);
        }
        __syncthreads();
        {
            float acc = b1p[tid];
            #pragma unroll
            for (int k = 0; k < 32; k++)
                acc = fmaf(sr[k], W1p[k * 256 + tid], acc);
            sh[tid] = fmaxf(acc, 0.0f);
        }
        __syncthreads();
        if (tid < 128) {
            float acc = b2p[tid];
            #pragma unroll 4
            for (int k = 0; k < 256; k++)
                acc = fmaf(sh[k], W2p[k * 128 + tid], acc);
            sphi[tid] = acc;
        }
        __syncthreads();
        for (int j = tid; j < 512; j += NTHR) {
            float acc = b1f[j];
            #pragma unroll 4
            for (int k = 0; k < 128; k++)
                acc = fmaf(sphi[k], W1f[(40 + k) * 512 + j], acc);
            g_b1eff[j] = acc;
        }
    }
}

// ---------------------------------------------------------------------------
// Main: CTA = 128 pixels as TWO 64-pixel tiles, 512 threads / 16 warps,
// each warp n32. A double-buffered in smem (2 x 64KB); tile 1's A production
// interleaved into tile 0's MMA mainloop. B QUAD-buffered in regs (distance
// 3); A fragments single-buffered with intra-step pipelined reloads.
// ---------------------------------------------------------------------------
#define SA_U4    4096                      /* per tile: 32kt x 4mt x 32lane uint4 */
#define OFF_SA   0
#define OFF_B1   (2 * SA_U4 * 16)          /* 131072 */
#define OFF_B2   (OFF_B1 + 2048)
#define OFF_W3   (OFF_B2 + 2048)
#define OFF_PART (OFF_W3 + 6144)
#define OFF_XY   (OFF_PART + 16 * 64 * 3 * 4)
#define SMEM_TOT (OFF_XY + 1024)

// Produce one A chunk (uint4) for pixel-tile with coord arrays sXt/sYt into
// sAdst. i in [0,8): chunk index for this thread.
__device__ __forceinline__ void produce_chunk(
    uint4* __restrict__ sAdst, const float* __restrict__ sB1,
    const int* __restrict__ sXt, const int* __restrict__ sYt,
    int tid, int i)
{
    const int pkc = tid >> 8;
    const int pkt = (tid >> 7) & 1;
    const int pmt = (tid >> 5) & 3;
    const int pln = tid & 31;
    const int pg  = pln >> 2, ptg = pln & 3;
    const int p0  = pmt * 16 + pg, p1 = p0 + 8;
    const float* ax0 = g_Ax + (size_t)sXt[p0] * 512;
    const float* ay0 = g_Ay + (size_t)sYt[p0] * 512;
    const float* ax1 = g_Ax + (size_t)sXt[p1] * 512;
    const float* ay1 = g_Ay + (size_t)sYt[p1] * 512;
    const int koff = pkt * 16 + ptg * 2;
    const int slot = (pkt * 4 + pmt) * 32 + pln;
    const int kc = i * 2 + pkc;
    const int kb = kc * 32 + koff;
    float2 xa = *(const float2*)(ax0 + kb),     ya = *(const float2*)(ay0 + kb);
    float2 xb = *(const float2*)(ax0 + kb + 8), yb = *(const float2*)(ay0 + kb + 8);
    float2 xc = *(const float2*)(ax1 + kb),     yc = *(const float2*)(ay1 + kb);
    float2 xd = *(const float2*)(ax1 + kb + 8), yd = *(const float2*)(ay1 + kb + 8);
    float2 ba = *(const float2*)(sB1 + kb),     bb = *(const float2*)(sB1 + kb + 8);
    uint4 v;
    v.x = h2u(relu_f(xa.x + ya.x + ba.x), relu_f(xa.y + ya.y + ba.y));
    v.y = h2u(relu_f(xc.x + yc.x + ba.x), relu_f(xc.y + yc.y + ba.y));
    v.z = h2u(relu_f(xb.x + yb.x + bb.x), relu_f(xb.y + yb.y + bb.y));
    v.w = h2u(relu_f(xd.x + yd.x + bb.x), relu_f(xd.y + yd.y + bb.y));
    sAdst[kc * 256 + slot] = v;
}

__global__ __launch_bounds__(MTHR, 1)
void nivr_mma_kernel(const float* __restrict__ coords,
                     const float* __restrict__ b2f,
                     const float* __restrict__ W3f,
                     const float* __restrict__ b3f,
                     float* __restrict__ out) {
    extern __shared__ char smem[];
    uint4* sA4   = (uint4*)(smem + OFF_SA);     // [2][4096]
    float* sB1   = (float*)(smem + OFF_B1);
    float* sB2   = (float*)(smem + OFF_B2);
    float* sW3   = (float*)(smem + OFF_W3);
    float* sPart = (float*)(smem + OFF_PART);   // [16][64][3]
    int*   sX    = (int*)(smem + OFF_XY);       // [128]
    int*   sY    = sX + 128;                    // [128]

    const int tid  = threadIdx.x;
    const int wid  = tid >> 5;            // warpN: 0..15 (cols wid*32..+31)
    const int lane = tid & 31;
    const int g    = lane >> 2;
    const int tg   = lane & 3;
    const int base = blockIdx.x * 128;

    if (tid < 128) {
        sX[tid] = (int)coords[(base + tid) * 2 + 0];
        sY[tid] = (int)coords[(base + tid) * 2 + 1];
    }
    for (int i = tid; i < 512;  i += MTHR) { sB1[i] = g_b1eff[i]; sB2[i] = b2f[i]; }
    for (int i = tid; i < 1536; i += MTHR) sW3[i] = W3f[i];
    __syncthreads();

    // ---- produce tile-0 A up front -----------------------------------------
    #pragma unroll 4
    for (int i = 0; i < 8; i++)
        produce_chunk(sA4, sB1, sX, sY, tid, i);

    const uint4* bbase = (const uint4*)g_W2H + wid * 2 * 32 + lane;

    #pragma unroll 1
    for (int t = 0; t < 2; t++) {
        __syncthreads();                   // A[t] ready; sPart safe to reuse
        const uint4* sAcur = sA4 + t * SA_U4;

        float acc[4][4][4];
        #pragma unroll
        for (int m = 0; m < 4; m++)
            #pragma unroll
            for (int n = 0; n < 4; n++)
                acc[m][n][0] = acc[m][n][1] = acc[m][n][2] = acc[m][n][3] = 0.0f;

        uint4 B0[2], B1[2], B2[2], B3[2];  // B[j] lives in B{j%4}
        uint4 af[4];                       // single-buffer, pipelined intra-step
        #pragma unroll
        for (int np = 0; np < 2; np++) {
            B0[np] = bbase[np * 32];
            B1[np] = bbase[1024 + np * 32];
            B2[np] = bbase[2048 + np * 32];
        }
        #pragma unroll
        for (int m = 0; m < 4; m++)
            af[m] = sAcur[m * 32 + lane];

// One k16-step: LDG B[KT+3] -> BLD; MMA m0/m1 with af, reload af[0..1] to
// kt+1; MMA m2/m3; reload af[2..3]. (WAR deps keep ordering legal.)
#define KSTEP_FULL(BUSE, BLD, KT)                                              \
    {                                                                          \
        _Pragma("unroll")                                                      \
        for (int np = 0; np < 2; np++)                                         \
            BLD[np] = bbase[((KT) + 3) * 1024 + np * 32];                      \
        _Pragma("unroll")                                                      \
        for (int np = 0; np < 2; np++) {                                       \
            MMA_F16(acc[0][np * 2 + 0], af[0], BUSE[np].x, BUSE[np].y);        \
            MMA_F16(acc[0][np * 2 + 1], af[0], BUSE[np].z, BUSE[np].w);        \
            MMA_F16(acc[1][np * 2 + 0], af[1], BUSE[np].x, BUSE[np].y);        \
            MMA_F16(acc[1][np * 2 + 1], af[1], BUSE[np].z, BUSE[np].w);        \
        }                                                                      \
        if ((KT) < 31) {                                                       \
            af[0] = sAcur[((KT) + 1) * 128 + lane];                            \
            af[1] = sAcur[((KT) + 1) * 128 + 32 + lane];                       \
        }                                                                      \
        _Pragma("unroll")                                                      \
        for (int np = 0; np < 2; np++) {                                       \
            MMA_F16(acc[2][np * 2 + 0], af[2], BUSE[np].x, BUSE[np].y);        \
            MMA_F16(acc[2][np * 2 + 1], af[2], BUSE[np].z, BUSE[np].w);        \
            MMA_F16(acc[3][np * 2 + 0], af[3], BUSE[np].x, BUSE[np].y);        \
            MMA_F16(acc[3][np * 2 + 1], af[3], BUSE[np].z, BUSE[np].w);        \
        }                                                                      \
        if ((KT) < 31) {                                                       \
            af[2] = sAcur[((KT) + 1) * 128 + 64 + lane];                       \
            af[3] = sAcur[((KT) + 1) * 128 + 96 + lane];                       \
        }                                                                      \
    }
#define KSTEP_NOLD(BUSE, KT)                                                   \
    {                                                                          \
        _Pragma("unroll")                                                      \
        for (int np = 0; np < 2; np++) {                                       \
            MMA_F16(acc[0][np * 2 + 0], af[0], BUSE[np].x, BUSE[np].y);        \
            MMA_F16(acc[0][np * 2 + 1], af[0], BUSE[np].z, BUSE[np].w);        \
            MMA_F16(acc[1][np * 2 + 0], af[1], BUSE[np].x, BUSE[np].y);        \
            MMA_F16(acc[1][np * 2 + 1], af[1], BUSE[np].z, BUSE[np].w);        \
        }                                                                      \
        if ((KT) < 31) {                                                       \
            af[0] = sAcur[((KT) + 1) * 128 + lane];                            \
            af[1] = sAcur[((KT) + 1) * 128 + 32 + lane];                       \
        }                                                                      \
        _Pragma("unroll")                                                      \
        for (int np = 0; np < 2; np++) {                                       \
            MMA_F16(acc[2][np * 2 + 0], af[2], BUSE[np].x, BUSE[np].y);        \
            MMA_F16(acc[2][np * 2 + 1], af[2], BUSE[np].z, BUSE[np].w);        \
            MMA_F16(acc[3][np * 2 + 0], af[3], BUSE[np].x, BUSE[np].y);        \
            MMA_F16(acc[3][np * 2 + 1], af[3], BUSE[np].z, BUSE[np].w);        \
        }                                                                      \
        if ((KT) < 31) {                                                       \
            af[2] = sAcur[((KT) + 1) * 128 + 64 + lane];                       \
            af[3] = sAcur[((KT) + 1) * 128 + 96 + lane];                       \
        }                                                                      \
    }

        // 28 full steps (unroll 4, B rotation period 4), weaving tile-1 A
        // production during tile 0; then 4 tail steps.
        int pi = 0;
        #pragma unroll 1
        for (int kt = 0; kt < 28; kt += 4) {
            KSTEP_FULL(B0, B3, kt);
            if (t == 0 && pi < 8) { produce_chunk(sA4 + SA_U4, sB1, sX + 64, sY + 64, tid, pi); pi++; }
            KSTEP_FULL(B1, B0, kt + 1);
            KSTEP_FULL(B2, B1, kt + 2);
            KSTEP_FULL(B3, B2, kt + 3);
        }
        KSTEP_FULL(B0, B3, 28);            // loads B[31]
        if (t == 0 && pi < 8) { produce_chunk(sA4 + SA_U4, sB1, sX + 64, sY + 64, tid, pi); pi++; }
        KSTEP_NOLD(B1, 29);
        KSTEP_NOLD(B2, 30);
        KSTEP_NOLD(B3, 31);

        // ---- epilogue: relu+bias, fold layer-3 into rgb partials -----------
        float rp[8][3];
        #pragma unroll
        for (int i = 0; i < 8; i++) rp[i][0] = rp[i][1] = rp[i][2] = 0.0f;

        #pragma unroll
        for (int m = 0; m < 4; m++)
            #pragma unroll
            for (int nt = 0; nt < 4; nt++) {
                int c0 = wid * 32 + nt * 8 + tg * 2;
                float h0 = relu_f(acc[m][nt][0] + sB2[c0]);
                float h1 = relu_f(acc[m][nt][1] + sB2[c0 + 1]);
                float h2 = relu_f(acc[m][nt][2] + sB2[c0]);
                float h3 = relu_f(acc[m][nt][3] + sB2[c0 + 1]);
                #pragma unroll
                for (int ch = 0; ch < 3; ch++) {
                    float w0 = sW3[c0 * 3 + ch], w1 = sW3[(c0 + 1) * 3 + ch];
                    rp[m * 2 + 0][ch] = fmaf(h0, w0, fmaf(h1, w1, rp[m * 2 + 0][ch]));
                    rp[m * 2 + 1][ch] = fmaf(h2, w0, fmaf(h3, w1, rp[m * 2 + 1][ch]));
                }
            }

        #pragma unroll
        for (int i = 0; i < 8; i++)
            #pragma unroll
            for (int ch = 0; ch < 3; ch++) {
                rp[i][ch] += __shfl_xor_sync(0xffffffffu, rp[i][ch], 1);
                rp[i][ch] += __shfl_xor_sync(0xffffffffu, rp[i][ch], 2);
            }
        if (tg == 0) {
            #pragma unroll
            for (int m = 0; m < 4; m++)
                #pragma unroll
                for (int rh = 0; rh < 2; rh++) {
                    int row = m * 16 + rh * 8 + g;
                    #pragma unroll
                    for (int ch = 0; ch < 3; ch++)
                        sPart[(wid * 64 + row) * 3 + ch] = rp[m * 2 + rh][ch];
                }
        }
        __syncthreads();
        if (tid < 64) {
            #pragma unroll
            for (int ch = 0; ch < 3; ch++) {
                float s = b3f[ch];
                #pragma unroll
                for (int w = 0; w < 16; w++) s += sPart[(w * 64 + tid) * 3 + ch];
                out[ch * N_PIX + base + t * 64 + tid] = s;
            }
        }
    }
}

// ---------------------------------------------------------------------------
extern "C" void kernel_launch(void* const* d_in, const int* in_sizes, int n_in,
                              void* d_out, int out_size) {
    const float* coords = (const float*)d_in[0];
    const float* W1p    = (const float*)d_in[1];
    const float* b1p    = (const float*)d_in[2];
    const float* W2p    = (const float*)d_in[3];
    const float* b2p    = (const float*)d_in[4];
    const float* W1f    = (const float*)d_in[5];
    const float* b1f    = (const float*)d_in[6];
    const float* W2f    = (const float*)d_in[7];
    const float* b2f    = (const float*)d_in[8];
    const float* W3f    = (const float*)d_in[9];
    const float* b3f    = (const float*)d_in[10];
    const int*   idx    = (const int*)d_in[11];
    float*       out    = (float*)d_out;

    cudaFuncSetAttribute(nivr_mma_kernel,
                         cudaFuncAttributeMaxDynamicSharedMemorySize, SMEM_TOT);

    nivr_prep_kernel<<<1537, NTHR>>>(W1p, b1p, W2p, b2p, W1f, b1f, W2f, idx);
    nivr_mma_kernel<<<N_PIX / 128, MTHR, SMEM_TOT>>>(coords, b2f, W3f, b3f, out);
}

// round 14
// speedup vs baseline: 1.0201x; 1.0201x over previous
#include <cuda_runtime.h>
#include <cuda_fp16.h>
#include <math.h>
#include <stdint.h>

#define N_PIX (512 * 512)
#define NTHR  256
#define MTHR  512

// ---------------------------------------------------------------------------
// Device scratch (no allocations allowed)
// ---------------------------------------------------------------------------
__device__ float    g_b1eff[512];        // b1f + phi_t @ W1f[40:,:]  (fp32!)
__device__ __half   g_AxH[512 * 512];    // posenc_x(c) @ W1f[0:20,:]  fp16
__device__ __half   g_AyH[512 * 512];    // posenc_y(c) @ W1f[20:40,:] fp16
__device__ uint32_t g_W2H[512 * 256];    // W2 fp16, uint4-fragment-major

// m16n8k16 fp16 mma, fp32 acc
#define MMA_F16(d, a, b0, b1)                                                  \
    asm volatile("mma.sync.aligned.m16n8k16.row.col.f32.f16.f16.f32 "          \
                 "{%0,%1,%2,%3},{%4,%5,%6,%7},{%8,%9},{%0,%1,%2,%3};"          \
                 : "+f"((d)[0]), "+f"((d)[1]), "+f"((d)[2]), "+f"((d)[3])      \
                 : "r"((a).x), "r"((a).y), "r"((a).z), "r"((a).w),             \
                   "r"(b0), "r"(b1))

__device__ __forceinline__ uint32_t h2u(float a, float b) {
    __half2 h = __floats2half2_rn(a, b);
    return *(uint32_t*)&h;
}
__device__ __forceinline__ float relu_f(float x) { return fmaxf(x, 0.0f); }

// ---------------------------------------------------------------------------
// Accurate sin/cos (flag-independent): Cody-Waite in double + Cephes fp32
// ---------------------------------------------------------------------------
__device__ __forceinline__ float trig_eval(float x, int cos_flag) {
    double d  = (double)x * 0.63661977236758134308;
    int    ki = __double2int_rn(d);
    float  rf = (float)((double)x - (double)ki * 1.57079632679489661923);
    int    q  = (ki + cos_flag) & 3;
    float  z  = rf * rf;
    float s = ((-1.9515295891e-4f * z + 8.3321608736e-3f) * z - 1.6666654611e-1f)
                  * z * rf + rf;
    float c = ((2.443315711809948e-5f * z - 1.388731625493765e-3f) * z
                  + 4.166664568298827e-2f) * z * z - 0.5f * z + 1.0f;
    float res = (q & 1) ? c : s;
    return (q & 2) ? -res : res;
}

// ---------------------------------------------------------------------------
// Prep (single launch, 1537 blocks): tables (fp16), W2H packing, time branch.
// W2H packing for element (n, k), value W2f[k*512+n]:
//   k16=k>>4, lane=(n&7)*4+((k&7)>>1), reg=(k>>3)&1, np=(n>>4), o=(n>>3)&1
//   uint4 index = (k16*32 + np)*32 + lane,  component = o*2 + reg
// ---------------------------------------------------------------------------
__global__ void nivr_prep_kernel(const float* __restrict__ W1p,
                                 const float* __restrict__ b1p,
                                 const float* __restrict__ W2p,
                                 const float* __restrict__ b2p,
                                 const float* __restrict__ W1f,
                                 const float* __restrict__ b1f,
                                 const float* __restrict__ W2f,
                                 const int*   __restrict__ idx_p) {
    const int b = blockIdx.x, tid = threadIdx.x;
    if (b < 1024) {
        const int axis = b >> 9;
        const int c    = b & 511;
        __shared__ float pe[20];
        if (tid < 20) {
            int l = tid % 10;
            float ang = (((float)c * (1.0f / 512.0f)) * (float)(1 << l))
                            * 3.14159265358979323846f;
            pe[tid] = trig_eval(ang, tid >= 10);
        }
        __syncthreads();
        const float*  Wr  = W1f + axis * 20 * 512;
        __half*       dst = (axis ? g_AyH : g_AxH) + c * 512;
        for (int j = tid; j < 512; j += NTHR) {
            float acc = 0.0f;
            #pragma unroll
            for (int f = 0; f < 20; f++)
                acc = fmaf(pe[f], Wr[f * 512 + j], acc);
            dst[j] = __float2half_rn(acc);
        }
    } else if (b < 1536) {
        const int n  = b - 1024;
        const int k  = tid * 2;             // even k; pack (k, k+1)
        float lo = W2f[(size_t)k * 512 + n];
        float hi = W2f[(size_t)(k + 1) * 512 + n];
        int k16  = k >> 4;
        int lane = (n & 7) * 4 + ((k & 7) >> 1);
        int reg  = (k >> 3) & 1;
        int idx4 = (k16 * 32 + (n >> 4)) * 32 + lane;
        int comp = ((n >> 3) & 1) * 2 + reg;
        g_W2H[idx4 * 4 + comp] = h2u(lo, hi);
    } else {
        __shared__ float sr[32];
        __shared__ float sh[256];
        __shared__ float sphi[128];
        float t = (float)(*idx_p) / 300.0f;
        if (tid < 32) {
            int l = tid & 15;
            float ang = (t * (float)(1 << l)) * 3.14159265358979323846f;
            sr[tid] = trig_eval(ang, tid >= 16);
        }
        __syncthreads();
        {
            float acc = b1p[tid];
            #pragma unroll
            for (int k = 0; k < 32; k++)
                acc = fmaf(sr[k], W1p[k * 256 + tid], acc);
            sh[tid] = fmaxf(acc, 0.0f);
        }
        __syncthreads();
        if (tid < 128) {
            float acc = b2p[tid];
            #pragma unroll 4
            for (int k = 0; k < 256; k++)
                acc = fmaf(sh[k], W2p[k * 128 + tid], acc);
            sphi[tid] = acc;
        }
        __syncthreads();
        for (int j = tid; j < 512; j += NTHR) {
            float acc = b1f[j];
            #pragma unroll 4
            for (int k = 0; k < 128; k++)
                acc = fmaf(sphi[k], W1f[(40 + k) * 512 + j], acc);
            g_b1eff[j] = acc;
        }
    }
}

// ---------------------------------------------------------------------------
// Main: CTA = 128 pixels as TWO 64-pixel tiles, 512 threads / 16 warps,
// each warp n32. A double-buffered in smem (2 x 64KB); tile 1's A production
// interleaved into tile 0's MMA mainloop. B triple-buffered (dist 2),
// A fragments double-buffered (dist 1) in regs. Tables read as fp16.
// ---------------------------------------------------------------------------
#define SA_U4    4096                      /* per tile: 32kt x 4mt x 32lane uint4 */
#define OFF_SA   0
#define OFF_B1   (2 * SA_U4 * 16)          /* 131072 */
#define OFF_B2   (OFF_B1 + 2048)
#define OFF_W3   (OFF_B2 + 2048)
#define OFF_PART (OFF_W3 + 6144)
#define OFF_XY   (OFF_PART + 16 * 64 * 3 * 4)
#define SMEM_TOT (OFF_XY + 1024)

// Produce one A chunk (uint4) for pixel-tile with coord arrays sXt/sYt into
// sAdst. i in [0,8): chunk index for this thread. Tables fp16; sum in fp32
// with exact b1eff (dominant h1 term) from smem.
__device__ __forceinline__ void produce_chunk(
    uint4* __restrict__ sAdst, const float* __restrict__ sB1,
    const int* __restrict__ sXt, const int* __restrict__ sYt,
    int tid, int i)
{
    const int pkc = tid >> 8;
    const int pkt = (tid >> 7) & 1;
    const int pmt = (tid >> 5) & 3;
    const int pln = tid & 31;
    const int pg  = pln >> 2, ptg = pln & 3;
    const int p0  = pmt * 16 + pg, p1 = p0 + 8;
    const __half2* ax0 = (const __half2*)(g_AxH + (size_t)sXt[p0] * 512);
    const __half2* ay0 = (const __half2*)(g_AyH + (size_t)sYt[p0] * 512);
    const __half2* ax1 = (const __half2*)(g_AxH + (size_t)sXt[p1] * 512);
    const __half2* ay1 = (const __half2*)(g_AyH + (size_t)sYt[p1] * 512);
    const int koff = pkt * 16 + ptg * 2;
    const int slot = (pkt * 4 + pmt) * 32 + pln;
    const int kc = i * 2 + pkc;
    const int kb = kc * 32 + koff;       // even
    const int k2 = kb >> 1;
    float2 xa = __half22float2(ax0[k2]),     ya = __half22float2(ay0[k2]);
    float2 xb = __half22float2(ax0[k2 + 4]), yb = __half22float2(ay0[k2 + 4]);
    float2 xc = __half22float2(ax1[k2]),     yc = __half22float2(ay1[k2]);
    float2 xd = __half22float2(ax1[k2 + 4]), yd = __half22float2(ay1[k2 + 4]);
    float2 ba = *(const float2*)(sB1 + kb),  bb = *(const float2*)(sB1 + kb + 8);
    uint4 v;
    v.x = h2u(relu_f(xa.x + ya.x + ba.x), relu_f(xa.y + ya.y + ba.y));
    v.y = h2u(relu_f(xc.x + yc.x + ba.x), relu_f(xc.y + yc.y + ba.y));
    v.z = h2u(relu_f(xb.x + yb.x + bb.x), relu_f(xb.y + yb.y + bb.y));
    v.w = h2u(relu_f(xd.x + yd.x + bb.x), relu_f(xd.y + yd.y + bb.y));
    sAdst[kc * 256 + slot] = v;
}

__global__ __launch_bounds__(MTHR, 1)
void nivr_mma_kernel(const float* __restrict__ coords,
                     const float* __restrict__ b2f,
                     const float* __restrict__ W3f,
                     const float* __restrict__ b3f,
                     float* __restrict__ out) {
    extern __shared__ char smem[];
    uint4* sA4   = (uint4*)(smem + OFF_SA);     // [2][4096]
    float* sB1   = (float*)(smem + OFF_B1);
    float* sB2   = (float*)(smem + OFF_B2);
    float* sW3   = (float*)(smem + OFF_W3);
    float* sPart = (float*)(smem + OFF_PART);   // [16][64][3]
    int*   sX    = (int*)(smem + OFF_XY);       // [128]
    int*   sY    = sX + 128;                    // [128]

    const int tid  = threadIdx.x;
    const int wid  = tid >> 5;            // warpN: 0..15 (cols wid*32..+31)
    const int lane = tid & 31;
    const int g    = lane >> 2;
    const int tg   = lane & 3;
    const int base = blockIdx.x * 128;

    if (tid < 128) {
        sX[tid] = (int)coords[(base + tid) * 2 + 0];
        sY[tid] = (int)coords[(base + tid) * 2 + 1];
    }
    for (int i = tid; i < 512;  i += MTHR) { sB1[i] = g_b1eff[i]; sB2[i] = b2f[i]; }
    for (int i = tid; i < 1536; i += MTHR) sW3[i] = W3f[i];
    __syncthreads();

    // ---- produce tile-0 A up front -----------------------------------------
    #pragma unroll 4
    for (int i = 0; i < 8; i++)
        produce_chunk(sA4, sB1, sX, sY, tid, i);

    const uint4* bbase = (const uint4*)g_W2H + wid * 2 * 32 + lane;

    #pragma unroll 1
    for (int t = 0; t < 2; t++) {
        __syncthreads();                   // A[t] ready; sPart safe to reuse
        const uint4* sAcur = sA4 + t * SA_U4;

        float acc[4][4][4];
        #pragma unroll
        for (int m = 0; m < 4; m++)
            #pragma unroll
            for (int n = 0; n < 4; n++)
                acc[m][n][0] = acc[m][n][1] = acc[m][n][2] = acc[m][n][3] = 0.0f;

        uint4 bb0[2], bb1[2], bb2[2];      // B[j] lives in bb[j % 3]
        uint4 afA[4], afB[4];              // af[kt]: afA even kt, afB odd kt
        #pragma unroll
        for (int np = 0; np < 2; np++) {
            bb0[np] = bbase[np * 32];
            bb1[np] = bbase[1024 + np * 32];
        }
        #pragma unroll
        for (int m = 0; m < 4; m++)
            afA[m] = sAcur[m * 32 + lane];

#define KSTEP_FULL(USEB, LDB, USEA, LDA, KT)                                   \
    {                                                                          \
        _Pragma("unroll")                                                      \
        for (int np = 0; np < 2; np++)                                         \
            LDB[np] = bbase[((KT) + 2) * 1024 + np * 32];                      \
        _Pragma("unroll")                                                      \
        for (int m = 0; m < 4; m++)                                            \
            LDA[m] = sAcur[((KT) + 1) * 128 + m * 32 + lane];                  \
        _Pragma("unroll")                                                      \
        for (int np = 0; np < 2; np++)                                         \
            _Pragma("unroll")                                                  \
            for (int m = 0; m < 4; m++) {                                      \
                MMA_F16(acc[m][np * 2 + 0], USEA[m], USEB[np].x, USEB[np].y);  \
                MMA_F16(acc[m][np * 2 + 1], USEA[m], USEB[np].z, USEB[np].w);  \
            }                                                                  \
    }
#define KSTEP_NOB(USEB, USEA, LDA, KT)                                         \
    {                                                                          \
        _Pragma("unroll")                                                      \
        for (int m = 0; m < 4; m++)                                            \
            LDA[m] = sAcur[((KT) + 1) * 128 + m * 32 + lane];                  \
        _Pragma("unroll")                                                      \
        for (int np = 0; np < 2; np++)                                         \
            _Pragma("unroll")                                                  \
            for (int m = 0; m < 4; m++) {                                      \
                MMA_F16(acc[m][np * 2 + 0], USEA[m], USEB[np].x, USEB[np].y);  \
                MMA_F16(acc[m][np * 2 + 1], USEA[m], USEB[np].z, USEB[np].w);  \
            }                                                                  \
    }
#define KSTEP_END(USEB, USEA)                                                  \
    {                                                                          \
        _Pragma("unroll")                                                      \
        for (int np = 0; np < 2; np++)                                         \
            _Pragma("unroll")                                                  \
            for (int m = 0; m < 4; m++) {                                      \
                MMA_F16(acc[m][np * 2 + 0], USEA[m], USEB[np].x, USEB[np].y);  \
                MMA_F16(acc[m][np * 2 + 1], USEA[m], USEB[np].z, USEB[np].w);  \
            }                                                                  \
    }

        // 6-step rotation; during tile 0, weave in tile-1 A production
        // (8 produce iterations at kt = 0,3,6,9,12,15,18,21).
        int pi = 0;
        #pragma unroll 1
        for (int kt = 0; kt < 30; kt += 6) {
            KSTEP_FULL(bb0, bb2, afA, afB, kt);
            if (t == 0 && pi < 8) { produce_chunk(sA4 + SA_U4, sB1, sX + 64, sY + 64, tid, pi); pi++; }
            KSTEP_FULL(bb1, bb0, afB, afA, kt + 1);
            KSTEP_FULL(bb2, bb1, afA, afB, kt + 2);
            KSTEP_FULL(bb0, bb2, afB, afA, kt + 3);
            if (t == 0 && pi < 8) { produce_chunk(sA4 + SA_U4, sB1, sX + 64, sY + 64, tid, pi); pi++; }
            KSTEP_FULL(bb1, bb0, afA, afB, kt + 4);
            KSTEP_FULL(bb2, bb1, afB, afA, kt + 5);
        }
        KSTEP_NOB(bb0, afA, afB, 30);
        KSTEP_END(bb1, afB);

        // ---- epilogue: relu+bias, fold layer-3 into rgb partials -----------
        float rp[8][3];
        #pragma unroll
        for (int i = 0; i < 8; i++) rp[i][0] = rp[i][1] = rp[i][2] = 0.0f;

        #pragma unroll
        for (int m = 0; m < 4; m++)
            #pragma unroll
            for (int nt = 0; nt < 4; nt++) {
                int c0 = wid * 32 + nt * 8 + tg * 2;
                float h0 = relu_f(acc[m][nt][0] + sB2[c0]);
                float h1 = relu_f(acc[m][nt][1] + sB2[c0 + 1]);
                float h2 = relu_f(acc[m][nt][2] + sB2[c0]);
                float h3 = relu_f(acc[m][nt][3] + sB2[c0 + 1]);
                #pragma unroll
                for (int ch = 0; ch < 3; ch++) {
                    float w0 = sW3[c0 * 3 + ch], w1 = sW3[(c0 + 1) * 3 + ch];
                    rp[m * 2 + 0][ch] = fmaf(h0, w0, fmaf(h1, w1, rp[m * 2 + 0][ch]));
                    rp[m * 2 + 1][ch] = fmaf(h2, w0, fmaf(h3, w1, rp[m * 2 + 1][ch]));
                }
            }

        #pragma unroll
        for (int i = 0; i < 8; i++)
            #pragma unroll
            for (int ch = 0; ch < 3; ch++) {
                rp[i][ch] += __shfl_xor_sync(0xffffffffu, rp[i][ch], 1);
                rp[i][ch] += __shfl_xor_sync(0xffffffffu, rp[i][ch], 2);
            }
        if (tg == 0) {
            #pragma unroll
            for (int m = 0; m < 4; m++)
                #pragma unroll
                for (int rh = 0; rh < 2; rh++) {
                    int row = m * 16 + rh * 8 + g;
                    #pragma unroll
                    for (int ch = 0; ch < 3; ch++)
                        sPart[(wid * 64 + row) * 3 + ch] = rp[m * 2 + rh][ch];
                }
        }
        __syncthreads();
        if (tid < 64) {
            #pragma unroll
            for (int ch = 0; ch < 3; ch++) {
                float s = b3f[ch];
                #pragma unroll
                for (int w = 0; w < 16; w++) s += sPart[(w * 64 + tid) * 3 + ch];
                out[ch * N_PIX + base + t * 64 + tid] = s;
            }
        }
    }
}

// ---------------------------------------------------------------------------
extern "C" void kernel_launch(void* const* d_in, const int* in_sizes, int n_in,
                              void* d_out, int out_size) {
    const float* coords = (const float*)d_in[0];
    const float* W1p    = (const float*)d_in[1];
    const float* b1p    = (const float*)d_in[2];
    const float* W2p    = (const float*)d_in[3];
    const float* b2p    = (const float*)d_in[4];
    const float* W1f    = (const float*)d_in[5];
    const float* b1f    = (const float*)d_in[6];
    const float* W2f    = (const float*)d_in[7];
    const float* b2f    = (const float*)d_in[8];
    const float* W3f    = (const float*)d_in[9];
    const float* b3f    = (const float*)d_in[10];
    const int*   idx    = (const int*)d_in[11];
    float*       out    = (float*)d_out;

    cudaFuncSetAttribute(nivr_mma_kernel,
                         cudaFuncAttributeMaxDynamicSharedMemorySize, SMEM_TOT);

    nivr_prep_kernel<<<1537, NTHR>>>(W1p, b1p, W2p, b2p, W1f, b1f, W2f, idx);
    nivr_mma_kernel<<<N_PIX / 128, MTHR, SMEM_TOT>>>(coords, b2f, W3f, b3f, out);
}

// round 15
// speedup vs baseline: 1.0981x; 1.0765x over previous
#include <cuda_runtime.h>
#include <cuda_fp16.h>
#include <math.h>
#include <stdint.h>

#define N_PIX (512 * 512)
#define NTHR  256
#define MTHR  512
#define TILES 4

// ---------------------------------------------------------------------------
// Device scratch (no allocations allowed)
// ---------------------------------------------------------------------------
__device__ float    g_b1eff[512];        // b1f + phi_t @ W1f[40:,:]  (fp32)
__device__ __half   g_AxH[512 * 512];    // posenc_x(c) @ W1f[0:20,:]  fp16
__device__ __half   g_AyH[512 * 512];    // posenc_y(c) @ W1f[20:40,:] fp16
__device__ uint32_t g_W2H[512 * 256];    // W2 fp16, uint4-fragment-major

// m16n8k16 fp16 mma, fp32 acc
#define MMA_F16(d, a, b0, b1)                                                  \
    asm volatile("mma.sync.aligned.m16n8k16.row.col.f32.f16.f16.f32 "          \
                 "{%0,%1,%2,%3},{%4,%5,%6,%7},{%8,%9},{%0,%1,%2,%3};"          \
                 : "+f"((d)[0]), "+f"((d)[1]), "+f"((d)[2]), "+f"((d)[3])      \
                 : "r"((a).x), "r"((a).y), "r"((a).z), "r"((a).w),             \
                   "r"(b0), "r"(b1))

__device__ __forceinline__ uint32_t h2u(float a, float b) {
    __half2 h = __floats2half2_rn(a, b);
    return *(uint32_t*)&h;
}
__device__ __forceinline__ float relu_f(float x) { return fmaxf(x, 0.0f); }

// ---------------------------------------------------------------------------
// Accurate sin/cos (flag-independent): Cody-Waite in double + Cephes fp32
// ---------------------------------------------------------------------------
__device__ __forceinline__ float trig_eval(float x, int cos_flag) {
    double d  = (double)x * 0.63661977236758134308;
    int    ki = __double2int_rn(d);
    float  rf = (float)((double)x - (double)ki * 1.57079632679489661923);
    int    q  = (ki + cos_flag) & 3;
    float  z  = rf * rf;
    float s = ((-1.9515295891e-4f * z + 8.3321608736e-3f) * z - 1.6666654611e-1f)
                  * z * rf + rf;
    float c = ((2.443315711809948e-5f * z - 1.388731625493765e-3f) * z
                  + 4.166664568298827e-2f) * z * z - 0.5f * z + 1.0f;
    float res = (q & 1) ? c : s;
    return (q & 2) ? -res : res;
}

// ---------------------------------------------------------------------------
// Prep (single launch, 1537 blocks): tables (fp16), W2H packing, time branch.
// ---------------------------------------------------------------------------
__global__ void nivr_prep_kernel(const float* __restrict__ W1p,
                                 const float* __restrict__ b1p,
                                 const float* __restrict__ W2p,
                                 const float* __restrict__ b2p,
                                 const float* __restrict__ W1f,
                                 const float* __restrict__ b1f,
                                 const float* __restrict__ W2f,
                                 const int*   __restrict__ idx_p) {
    const int b = blockIdx.x, tid = threadIdx.x;
    if (b < 1024) {
        const int axis = b >> 9;
        const int c    = b & 511;
        __shared__ float pe[20];
        if (tid < 20) {
            int l = tid % 10;
            float ang = (((float)c * (1.0f / 512.0f)) * (float)(1 << l))
                            * 3.14159265358979323846f;
            pe[tid] = trig_eval(ang, tid >= 10);
        }
        __syncthreads();
        const float*  Wr  = W1f + axis * 20 * 512;
        __half*       dst = (axis ? g_AyH : g_AxH) + c * 512;
        for (int j = tid; j < 512; j += NTHR) {
            float acc = 0.0f;
            #pragma unroll
            for (int f = 0; f < 20; f++)
                acc = fmaf(pe[f], Wr[f * 512 + j], acc);
            dst[j] = __float2half_rn(acc);
        }
    } else if (b < 1536) {
        const int n  = b - 1024;
        const int k  = tid * 2;             // even k; pack (k, k+1)
        float lo = W2f[(size_t)k * 512 + n];
        float hi = W2f[(size_t)(k + 1) * 512 + n];
        int k16  = k >> 4;
        int lane = (n & 7) * 4 + ((k & 7) >> 1);
        int reg  = (k >> 3) & 1;
        int idx4 = (k16 * 32 + (n >> 4)) * 32 + lane;
        int comp = ((n >> 3) & 1) * 2 + reg;
        g_W2H[idx4 * 4 + comp] = h2u(lo, hi);
    } else {
        __shared__ float sr[32];
        __shared__ float sh[256];
        __shared__ float sphi[128];
        float t = (float)(*idx_p) / 300.0f;
        if (tid < 32) {
            int l = tid & 15;
            float ang = (t * (float)(1 << l)) * 3.14159265358979323846f;
            sr[tid] = trig_eval(ang, tid >= 16);
        }
        __syncthreads();
        {
            float acc = b1p[tid];
            #pragma unroll
            for (int k = 0; k < 32; k++)
                acc = fmaf(sr[k], W1p[k * 256 + tid], acc);
            sh[tid] = fmaxf(acc, 0.0f);
        }
        __syncthreads();
        if (tid < 128) {
            float acc = b2p[tid];
            #pragma unroll 4
            for (int k = 0; k < 256; k++)
                acc = fmaf(sh[k], W2p[k * 128 + tid], acc);
            sphi[tid] = acc;
        }
        __syncthreads();
        for (int j = tid; j < 512; j += NTHR) {
            float acc = b1f[j];
            #pragma unroll 4
            for (int k = 0; k < 128; k++)
                acc = fmaf(sphi[k], W1f[(40 + k) * 512 + j], acc);
            g_b1eff[j] = acc;
        }
    }
}

// ---------------------------------------------------------------------------
// Main: CTA = 256 pixels as FOUR 64-pixel tiles, 512 threads / 16 warps,
// each warp n32. A ping-pong in smem (2 x 64KB); tile t+1's A production
// interleaved into tile t's MMA mainloop. B triple-buffered (dist 2),
// A fragments double-buffered (dist 1) in regs. Layer 3 via MMA (split-k
// across warps; C-fragments repacked as A-fragments in registers).
// ---------------------------------------------------------------------------
#define SA_U4    4096                      /* per buffer: 32kt x 4mt x 32lane */
#define OFF_SA   0
#define OFF_B1   (2 * SA_U4 * 16)          /* 131072 */
#define OFF_B2   (OFF_B1 + 2048)
#define OFF_W3   (OFF_B2 + 2048)
#define OFF_PART (OFF_W3 + 6144)
#define OFF_XY   (OFF_PART + 16 * 64 * 3 * 4)
#define SMEM_TOT (OFF_XY + 2048)

// Produce one A chunk (uint4) for pixel-tile with coord arrays sXt/sYt into
// sAdst. i in [0,8): chunk index for this thread. Tables fp16; sum in fp32
// with exact b1eff from smem.
__device__ __forceinline__ void produce_chunk(
    uint4* __restrict__ sAdst, const float* __restrict__ sB1,
    const int* __restrict__ sXt, const int* __restrict__ sYt,
    int tid, int i)
{
    const int pkc = tid >> 8;
    const int pkt = (tid >> 7) & 1;
    const int pmt = (tid >> 5) & 3;
    const int pln = tid & 31;
    const int pg  = pln >> 2, ptg = pln & 3;
    const int p0  = pmt * 16 + pg, p1 = p0 + 8;
    const __half2* ax0 = (const __half2*)(g_AxH + (size_t)sXt[p0] * 512);
    const __half2* ay0 = (const __half2*)(g_AyH + (size_t)sYt[p0] * 512);
    const __half2* ax1 = (const __half2*)(g_AxH + (size_t)sXt[p1] * 512);
    const __half2* ay1 = (const __half2*)(g_AyH + (size_t)sYt[p1] * 512);
    const int koff = pkt * 16 + ptg * 2;
    const int slot = (pkt * 4 + pmt) * 32 + pln;
    const int kc = i * 2 + pkc;
    const int kb = kc * 32 + koff;       // even
    const int k2 = kb >> 1;
    float2 xa = __half22float2(ax0[k2]),     ya = __half22float2(ay0[k2]);
    float2 xb = __half22float2(ax0[k2 + 4]), yb = __half22float2(ay0[k2 + 4]);
    float2 xc = __half22float2(ax1[k2]),     yc = __half22float2(ay1[k2]);
    float2 xd = __half22float2(ax1[k2 + 4]), yd = __half22float2(ay1[k2 + 4]);
    float2 ba = *(const float2*)(sB1 + kb),  bb = *(const float2*)(sB1 + kb + 8);
    uint4 v;
    v.x = h2u(relu_f(xa.x + ya.x + ba.x), relu_f(xa.y + ya.y + ba.y));
    v.y = h2u(relu_f(xc.x + yc.x + ba.x), relu_f(xc.y + yc.y + ba.y));
    v.z = h2u(relu_f(xb.x + yb.x + bb.x), relu_f(xb.y + yb.y + bb.y));
    v.w = h2u(relu_f(xd.x + yd.x + bb.x), relu_f(xd.y + yd.y + bb.y));
    sAdst[kc * 256 + slot] = v;
}

__global__ __launch_bounds__(MTHR, 1)
void nivr_mma_kernel(const float* __restrict__ coords,
                     const float* __restrict__ b2f,
                     const float* __restrict__ W3f,
                     const float* __restrict__ b3f,
                     float* __restrict__ out) {
    extern __shared__ char smem[];
    uint4* sA4   = (uint4*)(smem + OFF_SA);     // [2][4096]
    float* sB1   = (float*)(smem + OFF_B1);
    float* sB2   = (float*)(smem + OFF_B2);
    float* sW3   = (float*)(smem + OFF_W3);
    float* sPart = (float*)(smem + OFF_PART);   // [16][64][3]
    int*   sX    = (int*)(smem + OFF_XY);       // [256]
    int*   sY    = sX + 256;                    // [256]

    const int tid  = threadIdx.x;
    const int wid  = tid >> 5;            // warpN: 0..15 (cols wid*32..+31)
    const int lane = tid & 31;
    const int g    = lane >> 2;
    const int tg   = lane & 3;
    const int base = blockIdx.x * (64 * TILES);

    if (tid < 256) {
        sX[tid] = (int)coords[(base + tid) * 2 + 0];
        sY[tid] = (int)coords[(base + tid) * 2 + 1];
    }
    for (int i = tid; i < 512;  i += MTHR) { sB1[i] = g_b1eff[i]; sB2[i] = b2f[i]; }
    for (int i = tid; i < 1536; i += MTHR) sW3[i] = W3f[i];
    __syncthreads();

    // ---- produce tile-0 A up front -----------------------------------------
    #pragma unroll 4
    for (int i = 0; i < 8; i++)
        produce_chunk(sA4, sB1, sX, sY, tid, i);

    const uint4* bbase = (const uint4*)g_W2H + wid * 2 * 32 + lane;

    #pragma unroll 1
    for (int t = 0; t < TILES; t++) {
        __syncthreads();                   // A[t] ready; sPart safe to reuse
        const uint4* sAcur = sA4 + (t & 1) * SA_U4;
        uint4* sAnext = sA4 + ((t + 1) & 1) * SA_U4;
        const int* sXn = sX + (t + 1) * 64;
        const int* sYn = sY + (t + 1) * 64;

        float acc[4][4][4];
        #pragma unroll
        for (int m = 0; m < 4; m++)
            #pragma unroll
            for (int n = 0; n < 4; n++)
                acc[m][n][0] = acc[m][n][1] = acc[m][n][2] = acc[m][n][3] = 0.0f;

        uint4 bb0[2], bb1[2], bb2[2];      // B[j] lives in bb[j % 3]
        uint4 afA[4], afB[4];              // af[kt]: afA even kt, afB odd kt
        #pragma unroll
        for (int np = 0; np < 2; np++) {
            bb0[np] = bbase[np * 32];
            bb1[np] = bbase[1024 + np * 32];
        }
        #pragma unroll
        for (int m = 0; m < 4; m++)
            afA[m] = sAcur[m * 32 + lane];

#define KSTEP_FULL(USEB, LDB, USEA, LDA, KT)                                   \
    {                                                                          \
        _Pragma("unroll")                                                      \
        for (int np = 0; np < 2; np++)                                         \
            LDB[np] = bbase[((KT) + 2) * 1024 + np * 32];                      \
        _Pragma("unroll")                                                      \
        for (int m = 0; m < 4; m++)                                            \
            LDA[m] = sAcur[((KT) + 1) * 128 + m * 32 + lane];                  \
        _Pragma("unroll")                                                      \
        for (int np = 0; np < 2; np++)                                         \
            _Pragma("unroll")                                                  \
            for (int m = 0; m < 4; m++) {                                      \
                MMA_F16(acc[m][np * 2 + 0], USEA[m], USEB[np].x, USEB[np].y);  \
                MMA_F16(acc[m][np * 2 + 1], USEA[m], USEB[np].z, USEB[np].w);  \
            }                                                                  \
    }
#define KSTEP_NOB(USEB, USEA, LDA, KT)                                         \
    {                                                                          \
        _Pragma("unroll")                                                      \
        for (int m = 0; m < 4; m++)                                            \
            LDA[m] = sAcur[((KT) + 1) * 128 + m * 32 + lane];                  \
        _Pragma("unroll")                                                      \
        for (int np = 0; np < 2; np++)                                         \
            _Pragma("unroll")                                                  \
            for (int m = 0; m < 4; m++) {                                      \
                MMA_F16(acc[m][np * 2 + 0], USEA[m], USEB[np].x, USEB[np].y);  \
                MMA_F16(acc[m][np * 2 + 1], USEA[m], USEB[np].z, USEB[np].w);  \
            }                                                                  \
    }
#define KSTEP_END(USEB, USEA)                                                  \
    {                                                                          \
        _Pragma("unroll")                                                      \
        for (int np = 0; np < 2; np++)                                         \
            _Pragma("unroll")                                                  \
            for (int m = 0; m < 4; m++) {                                      \
                MMA_F16(acc[m][np * 2 + 0], USEA[m], USEB[np].x, USEB[np].y);  \
                MMA_F16(acc[m][np * 2 + 1], USEA[m], USEB[np].z, USEB[np].w);  \
            }                                                                  \
    }

        // 6-step rotation; weave next tile's A production (8 iterations).
        int pi = 0;
        #pragma unroll 1
        for (int kt = 0; kt < 30; kt += 6) {
            KSTEP_FULL(bb0, bb2, afA, afB, kt);
            if (t < TILES - 1 && pi < 8) { produce_chunk(sAnext, sB1, sXn, sYn, tid, pi); pi++; }
            KSTEP_FULL(bb1, bb0, afB, afA, kt + 1);
            KSTEP_FULL(bb2, bb1, afA, afB, kt + 2);
            KSTEP_FULL(bb0, bb2, afB, afA, kt + 3);
            if (t < TILES - 1 && pi < 8) { produce_chunk(sAnext, sB1, sXn, sYn, tid, pi); pi++; }
            KSTEP_FULL(bb1, bb0, afA, afB, kt + 4);
            KSTEP_FULL(bb2, bb1, afB, afA, kt + 5);
        }
        KSTEP_NOB(bb0, afA, afB, 30);
        KSTEP_END(bb1, afB);

        // ---- layer-3 via MMA: split-k across warps --------------------------
        // C-frag of acc == A-frag halves: pack relu(acc+b2) in registers.
        // B3 = W3[k16, n8] fragment (n = channel = g; zero for g >= 3).
        float acc3[4][4];
        #pragma unroll
        for (int m = 0; m < 4; m++)
            acc3[m][0] = acc3[m][1] = acc3[m][2] = acc3[m][3] = 0.0f;

        #pragma unroll
        for (int ktl = 0; ktl < 2; ktl++) {
            const int K0 = wid * 32 + ktl * 16;
            uint32_t b3r0 = 0, b3r1 = 0;
            if (g < 3) {
                b3r0 = h2u(sW3[(K0 + tg * 2) * 3 + g],
                           sW3[(K0 + tg * 2 + 1) * 3 + g]);
                b3r1 = h2u(sW3[(K0 + 8 + tg * 2) * 3 + g],
                           sW3[(K0 + 9 + tg * 2) * 3 + g]);
            }
            const float bc0 = sB2[K0 + tg * 2],     bc1 = sB2[K0 + tg * 2 + 1];
            const float bc2 = sB2[K0 + 8 + tg * 2], bc3 = sB2[K0 + 9 + tg * 2];
            #pragma unroll
            for (int m = 0; m < 4; m++) {
                const int n0 = ktl * 2, n1 = ktl * 2 + 1;
                uint4 a;
                a.x = h2u(relu_f(acc[m][n0][0] + bc0), relu_f(acc[m][n0][1] + bc1));
                a.y = h2u(relu_f(acc[m][n0][2] + bc0), relu_f(acc[m][n0][3] + bc1));
                a.z = h2u(relu_f(acc[m][n1][0] + bc2), relu_f(acc[m][n1][1] + bc3));
                a.w = h2u(relu_f(acc[m][n1][2] + bc2), relu_f(acc[m][n1][3] + bc3));
                MMA_F16(acc3[m], a, b3r0, b3r1);
            }
        }

        // scatter per-warp rgb partials (channel = tg*2 + {0,1}; tg<2 useful)
        if (tg == 0) {
            #pragma unroll
            for (int m = 0; m < 4; m++) {
                int r0 = m * 16 + g, r1 = r0 + 8;
                sPart[(wid * 64 + r0) * 3 + 0] = acc3[m][0];
                sPart[(wid * 64 + r0) * 3 + 1] = acc3[m][1];
                sPart[(wid * 64 + r1) * 3 + 0] = acc3[m][2];
                sPart[(wid * 64 + r1) * 3 + 1] = acc3[m][3];
            }
        } else if (tg == 1) {
            #pragma unroll
            for (int m = 0; m < 4; m++) {
                int r0 = m * 16 + g, r1 = r0 + 8;
                sPart[(wid * 64 + r0) * 3 + 2] = acc3[m][0];
                sPart[(wid * 64 + r1) * 3 + 2] = acc3[m][2];
            }
        }
        __syncthreads();
        if (tid < 64) {
            #pragma unroll
            for (int ch = 0; ch < 3; ch++) {
                float s = b3f[ch];
                #pragma unroll
                for (int w = 0; w < 16; w++) s += sPart[(w * 64 + tid) * 3 + ch];
                out[ch * N_PIX + base + t * 64 + tid] = s;
            }
        }
    }
}

// ---------------------------------------------------------------------------
extern "C" void kernel_launch(void* const* d_in, const int* in_sizes, int n_in,
                              void* d_out, int out_size) {
    const float* coords = (const float*)d_in[0];
    const float* W1p    = (const float*)d_in[1];
    const float* b1p    = (const float*)d_in[2];
    const float* W2p    = (const float*)d_in[3];
    const float* b2p    = (const float*)d_in[4];
    const float* W1f    = (const float*)d_in[5];
    const float* b1f    = (const float*)d_in[6];
    const float* W2f    = (const float*)d_in[7];
    const float* b2f    = (const float*)d_in[8];
    const float* W3f    = (const float*)d_in[9];
    const float* b3f    = (const float*)d_in[10];
    const int*   idx    = (const int*)d_in[11];
    float*       out    = (float*)d_out;

    cudaFuncSetAttribute(nivr_mma_kernel,
                         cudaFuncAttributeMaxDynamicSharedMemorySize, SMEM_TOT);

    nivr_prep_kernel<<<1537, NTHR>>>(W1p, b1p, W2p, b2p, W1f, b1f, W2f, idx);
    nivr_mma_kernel<<<N_PIX / (64 * TILES), MTHR, SMEM_TOT>>>(coords, b2f, W3f,
                                                              b3f, out);
}